// round 1
// baseline (speedup 1.0000x reference)
#include <cuda_runtime.h>

// TemporalDecay: out = m*h + (1-m)*(g*h_fwd + (1-g)*h)
//              = h + (1-m)*g*(h_fwd - h)
// with g = exp(-relu(delta*W + b)), delta integer in [1,4],
// h_fwd[b,t,j] = h[b, t-(delta[b,t,j%D]-1), j].

static constexpr int Bq = 32, Tq = 2048, Dq = 64, Kq = 4;
static constexpr int C = Kq * Dq;                 // 256 channels
static constexpr int TOTAL4 = Bq * Tq * C / 4;    // 4,194,304 float4s
static constexpr int THREADS = 256;
static constexpr int ITERS = 4;
static constexpr int BLOCKS = TOTAL4 / (THREADS * ITERS);  // 4096

// gamma table: [delta-1][j], 4*256 floats = 4KB. Device global (no allocs allowed).
__device__ float g_gamma[4 * C];

__global__ void gamma_precompute_kernel(const float* __restrict__ W,
                                        const float* __restrict__ bias) {
    int j = threadIdx.x;  // 0..255
    float w = W[j];
    float bb = bias[j];
#pragma unroll
    for (int dm = 0; dm < 4; dm++) {
        float x = fmaxf(fmaf((float)(dm + 1), w, bb), 0.0f);
        g_gamma[dm * C + j] = __expf(-x);
    }
}

__global__ void __launch_bounds__(THREADS) decay_kernel(
    const float* __restrict__ h_a,     // [B,T,256]
    const float* __restrict__ deltas,  // [B,T,64]
    const float* __restrict__ Mmask,   // [B,T,64]
    float* __restrict__ out)           // [B,T,256]
{
    __shared__ float s_gamma[4 * C];
    // 256 threads each copy one float4 -> 4KB table staged (L2-resident source)
    ((float4*)s_gamma)[threadIdx.x] = ((const float4*)g_gamma)[threadIdx.x];
    __syncthreads();

    const int stride = gridDim.x * blockDim.x;
    int i = blockIdx.x * blockDim.x + threadIdx.x;

#pragma unroll
    for (int it = 0; it < ITERS; it++, i += stride) {
        const int row  = i >> 6;         // which (b,t): 64 float4s per row of 256
        const int col4 = i & 63;
        const int j    = col4 << 2;      // channel of .x
        const int dq   = row * 16 + (col4 & 15);  // float4 index into [B,T,64]

        const float4 ha = __ldg((const float4*)h_a + i);
        const float4 dl = __ldg((const float4*)deltas + dq);
        const float4 mm = __ldg((const float4*)Mmask + dq);

        const int d0 = (int)dl.x, d1 = (int)dl.y, d2 = (int)dl.z, d3 = (int)dl.w;

        // gather: h_a[(row - (d-1))*C + j + sub]; delta<=t+1 keeps it in-batch
        const int base = row * C + j;
        const float f0 = __ldg(h_a + base + 0 - (d0 - 1) * C);
        const float f1 = __ldg(h_a + base + 1 - (d1 - 1) * C);
        const float f2 = __ldg(h_a + base + 2 - (d2 - 1) * C);
        const float f3 = __ldg(h_a + base + 3 - (d3 - 1) * C);

        const float g0 = s_gamma[(d0 - 1) * C + j + 0];
        const float g1 = s_gamma[(d1 - 1) * C + j + 1];
        const float g2 = s_gamma[(d2 - 1) * C + j + 2];
        const float g3 = s_gamma[(d3 - 1) * C + j + 3];

        float4 o;
        o.x = fmaf((1.0f - mm.x) * g0, f0 - ha.x, ha.x);
        o.y = fmaf((1.0f - mm.y) * g1, f1 - ha.y, ha.y);
        o.z = fmaf((1.0f - mm.z) * g2, f2 - ha.z, ha.z);
        o.w = fmaf((1.0f - mm.w) * g3, f3 - ha.w, ha.w);

        ((float4*)out)[i] = o;
    }
}

extern "C" void kernel_launch(void* const* d_in, const int* in_sizes, int n_in,
                              void* d_out, int out_size) {
    const float* h_a    = (const float*)d_in[0];
    const float* deltas = (const float*)d_in[1];
    const float* Mmask  = (const float*)d_in[2];
    const float* W      = (const float*)d_in[3];
    const float* b      = (const float*)d_in[4];
    float* out = (float*)d_out;

    gamma_precompute_kernel<<<1, C>>>(W, b);
    decay_kernel<<<BLOCKS, THREADS>>>(h_a, deltas, Mmask, out);
}